// round 4
// baseline (speedup 1.0000x reference)
#include <cuda_runtime.h>
#include <cstdint>

#define NQ 4
#define NL 6
#define NC 10
#define DIM 512
#define HPI_F 1.57079632679489661923f

#define THREADS 128
#define ROWS 64   // rows per block; 2 threads per row in phase 2

typedef unsigned long long ull;

// packed f32x2 helpers
__device__ __forceinline__ void fma2(ull& d, ull a, ull b, ull c) {
    asm("fma.rn.f32x2 %0, %1, %2, %3;" : "=l"(d) : "l"(a), "l"(b), "l"(c));
}
__device__ __forceinline__ ull pack2(float lo, float hi) {
    ull r;
    asm("mov.b64 %0, {%1, %2};" : "=l"(r) : "r"(__float_as_uint(lo)), "r"(__float_as_uint(hi)));
    return r;
}
__device__ __forceinline__ void unpack2(ull v, float& lo, float& hi) {
    unsigned int a, b;
    asm("mov.b64 {%0, %1}, %2;" : "=r"(a), "=r"(b) : "l"(v));
    lo = __uint_as_float(a); hi = __uint_as_float(b);
}

// ---------------------------------------------------------------------------
// One fused kernel, grid = B/64 CTAs of 128 threads.
// Phase 0: 4 warps build U (each warp evolves 2 basis columns x 2 passes).
// Phase 1: GEMV. warp = (rowgroup g, colhalf h). Warp does 32 rows over its
//          256 columns with f32x2 FMAs, depth-2 row prefetch, 2-level shfl
//          reduce -> 8 partials per row-half into smem.
// Phase 2: 2 threads per row: sum 16 partials -> pre -> tanh -> angles ->
//          product state v -> each thread does 8 of 16 rows of U v -> partial
//          Z-expectations, combined via smem -> post linear -> coalesced out.
// ---------------------------------------------------------------------------
__global__ __launch_bounds__(THREADS, 6) void vqc_fused_kernel(
    const float* __restrict__ x,
    const float* __restrict__ Wpre,
    const float* __restrict__ bpre,
    const float* __restrict__ qw,
    const float* __restrict__ Wpost,
    const float* __restrict__ bpost,
    float* __restrict__ out)
{
    __shared__ float  sg[24][8];
    __shared__ float2 sU[256];                 // column-major [j][i]
    __shared__ float4 spart[ROWS][17];         // 16 partials/row, pad 17
    __shared__ float4 sq[ROWS];                // partial Z-expectations
    __shared__ float  souts[ROWS * NC];

    const int tid  = threadIdx.x;
    const int lane = tid & 31;
    const int warp = tid >> 5;
    const int row0 = blockIdx.x * ROWS;

    const int g = warp >> 1;        // row group: rows g*32 .. g*32+31
    const int h = warp & 1;         // column half: cols h*256 ..

    // ---- issue first GEMV prefetches before the U chain ----
    const float4* x4 = (const float4*)x;
    const float4* xp = x4 + (size_t)(row0 + g * 32) * 128 + h * 64 + lane;

    float4 c0 = __ldcs(xp);
    float4 c1 = __ldcs(xp + 32);
    float4 n0 = __ldcs(xp + 128);
    float4 n1 = __ldcs(xp + 160);

    // W_pre for this column half, packed as f32x2 pairs
    const float4* W4 = (const float4*)Wpre;   // [4][128] float4
    ull wp[4][4];                              // [out][j*2+pair]
#pragma unroll
    for (int w = 0; w < 4; w++)
#pragma unroll
        for (int j = 0; j < 2; j++) {
            float4 t = W4[w * 128 + h * 64 + j * 32 + lane];
            wp[w][j * 2 + 0] = pack2(t.x, t.y);
            wp[w][j * 2 + 1] = pack2(t.z, t.w);
        }

    // ---- Phase 0: gate coefficients, then U via shfl evolution ----
    if (tid < 24) {
        float phi = qw[tid * 3 + 0];
        float th  = qw[tid * 3 + 1];
        float om  = qw[tid * 3 + 2];
        float st, ct; sincosf(0.5f * th, &st, &ct);
        float sa, ca; sincosf(0.5f * (phi + om), &sa, &ca);
        float sb, cb; sincosf(0.5f * (phi - om), &sb, &cb);
        sg[tid][0] =  ca * ct;  sg[tid][1] = -sa * ct;   // g00
        sg[tid][2] = -cb * st;  sg[tid][3] = -sb * st;   // g01
        sg[tid][4] =  cb * st;  sg[tid][5] = -sb * st;   // g10
        sg[tid][6] =  ca * ct;  sg[tid][7] =  sa * ct;   // g11
    }
    __syncthreads();

#pragma unroll
    for (int p = 0; p < 2; p++) {
        int i = lane & 15;
        int j = warp * 4 + p * 2 + (lane >> 4);
        float re = (i == j) ? 1.0f : 0.0f;
        float im = 0.0f;
#pragma unroll
        for (int l = 0; l < NL; l++) {
#pragma unroll
            for (int w = 0; w < NQ; w++) {
                const float* gg = sg[l * NQ + w];
                int m = 8 >> w;
                float pre_ = __shfl_xor_sync(0xffffffffu, re, m);
                float pim  = __shfl_xor_sync(0xffffffffu, im, m);
                bool low = (i & m) == 0;
                float orr = low ? gg[0] : gg[6];
                float oii = low ? gg[1] : gg[7];
                float crr = low ? gg[2] : gg[4];
                float cii = low ? gg[3] : gg[5];
                float nre = orr * re - oii * im + crr * pre_ - cii * pim;
                float nim = orr * im + oii * re + crr * pim + cii * pre_;
                re = nre; im = nim;
            }
            int r = l % (NQ - 1) + 1;
#pragma unroll
            for (int w = 0; w < NQ; w++) {
                int cmask = 8 >> w;
                int tmask = 8 >> ((w + r) & 3);
                int src_i = (i & cmask) ? (i ^ tmask) : i;
                int srcLane = (lane & 16) | src_i;
                re = __shfl_sync(0xffffffffu, re, srcLane);
                im = __shfl_sync(0xffffffffu, im, srcLane);
            }
        }
        sU[j * 16 + i] = make_float2(re, im);
    }

    // ---- Phase 1: GEMV over 32 rows, 256 cols per warp ----
#pragma unroll 4
    for (int rr = 0; rr < 32; rr++) {
        float4 m0, m1;
        if (rr + 2 < 32) {
            m0 = __ldcs(xp + (rr + 2) * 128);
            m1 = __ldcs(xp + (rr + 2) * 128 + 32);
        }
        ull ax = pack2(c0.x, c0.y), ay = pack2(c0.z, c0.w);
        ull bx = pack2(c1.x, c1.y), by = pack2(c1.z, c1.w);

        float ac[4];
#pragma unroll
        for (int w = 0; w < 4; w++) {
            ull a2 = pack2(0.0f, 0.0f);
            fma2(a2, ax, wp[w][0], a2);
            fma2(a2, ay, wp[w][1], a2);
            fma2(a2, bx, wp[w][2], a2);
            fma2(a2, by, wp[w][3], a2);
            float lo, hi; unpack2(a2, lo, hi);
            ac[w] = lo + hi;
        }
#pragma unroll
        for (int w = 0; w < 4; w++) {
            ac[w] += __shfl_xor_sync(0xffffffffu, ac[w], 16);
            ac[w] += __shfl_xor_sync(0xffffffffu, ac[w], 8);
        }
        if (lane < 8)
            spart[g * 32 + rr][h * 8 + lane] = make_float4(ac[0], ac[1], ac[2], ac[3]);

        c0 = n0; c1 = n1; n0 = m0; n1 = m1;
    }
    __syncthreads();

    // ---- Phase 2: 2 threads per row ----
    const int row = tid & 63;
    const int ih  = tid >> 6;        // amplitude half: i in [ih*8, ih*8+8)

    float4 pre4 = make_float4(bpre[0], bpre[1], bpre[2], bpre[3]);
#pragma unroll
    for (int k = 0; k < 16; k++) {
        float4 p = spart[row][k];
        pre4.x += p.x; pre4.y += p.y; pre4.z += p.z; pre4.w += p.w;
    }

    float cw[4], sw[4];
    {
        float pv[4] = {pre4.x, pre4.y, pre4.z, pre4.w};
#pragma unroll
        for (int w = 0; w < 4; w++) {
            float e = __expf(2.0f * pv[w]);
            float t = 1.0f - __fdividef(2.0f, e + 1.0f);   // tanh
            float hh = HPI_F * t;
            sw[w] = __sinf(hh);
            cw[w] = __cosf(hh);
        }
    }

    float p01[4], p23[4], v[16];
    p01[0] = cw[0] * cw[1]; p01[1] = cw[0] * sw[1];
    p01[2] = sw[0] * cw[1]; p01[3] = sw[0] * sw[1];
    p23[0] = cw[2] * cw[3]; p23[1] = cw[2] * sw[3];
    p23[2] = sw[2] * cw[3]; p23[3] = sw[2] * sw[3];
#pragma unroll
    for (int a = 0; a < 4; a++)
#pragma unroll
        for (int b = 0; b < 4; b++)
            v[a * 4 + b] = p01[a] * p23[b];

    // 8 of 16 rows of U v
    ull acc64[8];
#pragma unroll
    for (int i = 0; i < 8; i++) acc64[i] = 0ull;
    const ull* sU64 = (const ull*)sU;
#pragma unroll
    for (int jcol = 0; jcol < 16; jcol++) {
        ull vj2 = pack2(v[jcol], v[jcol]);
#pragma unroll
        for (int i = 0; i < 8; i++)
            fma2(acc64[i], sU64[jcol * 16 + ih * 8 + i], vj2, acc64[i]);
    }

    float pb[8];
#pragma unroll
    for (int i = 0; i < 8; i++) {
        float re, im; unpack2(acc64[i], re, im);
        pb[i] = re * re + im * im;
    }

    float q[4];
#pragma unroll
    for (int w = 0; w < 4; w++) {
        int m = 8 >> w;
        float s = 0.0f;
#pragma unroll
        for (int i = 0; i < 8; i++) {
            int gi = ih * 8 + i;
            s += (gi & m) ? -pb[i] : pb[i];
        }
        q[w] = s;
    }

    if (ih == 1) sq[row] = make_float4(q[0], q[1], q[2], q[3]);
    __syncthreads();
    if (ih == 0) {
        float4 qp = sq[row];
        q[0] += qp.x; q[1] += qp.y; q[2] += qp.z; q[3] += qp.w;
#pragma unroll
        for (int c = 0; c < NC; c++) {
            float o = bpost[c];
#pragma unroll
            for (int w = 0; w < 4; w++) o = fmaf(q[w], Wpost[c * 4 + w], o);
            souts[row * NC + c] = o;
        }
    }
    __syncthreads();

    size_t obase = (size_t)row0 * NC;
    for (int i = tid; i < ROWS * NC; i += THREADS)
        out[obase + i] = souts[i];
}

// ---------------------------------------------------------------------------
extern "C" void kernel_launch(void* const* d_in, const int* in_sizes, int n_in,
                              void* d_out, int out_size) {
    const float* x     = (const float*)d_in[0];
    const float* Wpre  = (const float*)d_in[1];
    const float* bpre  = (const float*)d_in[2];
    const float* qw    = (const float*)d_in[3];
    const float* Wpost = (const float*)d_in[4];
    const float* bpost = (const float*)d_in[5];
    float* out = (float*)d_out;

    int B = in_sizes[0] / DIM;   // 65536
    vqc_fused_kernel<<<B / ROWS, THREADS>>>(x, Wpre, bpre, qw, Wpost, bpost, out);
}

// round 5
// speedup vs baseline: 1.0988x; 1.0988x over previous
#include <cuda_runtime.h>
#include <cstdint>

#define NQ 4
#define NL 6
#define NC 10
#define DIM 512
#define HPI_F 1.57079632679489661923f

#define THREADS 256
#define ROWS 256

typedef unsigned long long ull;

__device__ __forceinline__ void fma2(ull& d, ull a, ull b, ull c) {
    asm("fma.rn.f32x2 %0, %1, %2, %3;" : "=l"(d) : "l"(a), "l"(b), "l"(c));
}
__device__ __forceinline__ ull pack2(float lo, float hi) {
    ull r;
    asm("mov.b64 %0, {%1, %2};" : "=l"(r) : "r"(__float_as_uint(lo)), "r"(__float_as_uint(hi)));
    return r;
}
__device__ __forceinline__ void unpack2(ull v, float& lo, float& hi) {
    unsigned int a, b;
    asm("mov.b64 {%0, %1}, %2;" : "=r"(a), "=r"(b) : "l"(v));
    lo = __uint_as_float(a); hi = __uint_as_float(b);
}

// compute one row's partial dot products from a 4x float4 buffer + smem W,
// reduce 2 levels, store 8 partials.
__device__ __forceinline__ void gemv_row(
    const float4 xv[4], const float4* __restrict__ sW,
    float4* __restrict__ spart, int lrow, int lane)
{
    float acc[4] = {0.f, 0.f, 0.f, 0.f};
#pragma unroll
    for (int jj = 0; jj < 4; jj++) {
#pragma unroll
        for (int w = 0; w < 4; w++) {
            float4 wv = sW[w * 128 + jj * 32 + lane];
            acc[w] = fmaf(xv[jj].x, wv.x, acc[w]);
            acc[w] = fmaf(xv[jj].y, wv.y, acc[w]);
            acc[w] = fmaf(xv[jj].z, wv.z, acc[w]);
            acc[w] = fmaf(xv[jj].w, wv.w, acc[w]);
        }
    }
#pragma unroll
    for (int w = 0; w < 4; w++) {
        acc[w] += __shfl_xor_sync(0xffffffffu, acc[w], 16);
        acc[w] += __shfl_xor_sync(0xffffffffu, acc[w], 8);
    }
    if (lane < 8)
        spart[lrow * 8 + lane] = make_float4(acc[0], acc[1], acc[2], acc[3]);
}

__global__ __launch_bounds__(THREADS, 2) void vqc_fused_kernel(
    const float* __restrict__ x,
    const float* __restrict__ Wpre,
    const float* __restrict__ bpre,
    const float* __restrict__ qw,
    const float* __restrict__ Wpost,
    const float* __restrict__ bpost,
    float* __restrict__ out)
{
    __shared__ float  sg[24][8];
    __shared__ float4 sW[512];              // W_pre: [4][128] float4
    __shared__ float2 sU[256];              // U column-major [j][i]
    __shared__ float4 spart[ROWS * 8];      // 32KB partials
    __shared__ float  souts[ROWS * NC];

    const int tid  = threadIdx.x;
    const int lane = tid & 31;
    const int warp = tid >> 5;
    const int row0 = blockIdx.x * ROWS;
    const int wrow0 = row0 + warp * 32;

    const float4* x4 = (const float4*)x;
    const float4* xp = x4 + (size_t)wrow0 * 128 + lane;

    // ---- prologue: issue 3 rows of prefetch immediately ----
    float4 A[4], B[4], C[4], D[4];
#pragma unroll
    for (int jj = 0; jj < 4; jj++) A[jj] = xp[0 * 128 + jj * 32];
#pragma unroll
    for (int jj = 0; jj < 4; jj++) B[jj] = xp[1 * 128 + jj * 32];
#pragma unroll
    for (int jj = 0; jj < 4; jj++) C[jj] = xp[2 * 128 + jj * 32];

    // gate coefficients
    if (tid < 24) {
        float phi = qw[tid * 3 + 0];
        float th  = qw[tid * 3 + 1];
        float om  = qw[tid * 3 + 2];
        float st, ct; sincosf(0.5f * th, &st, &ct);
        float sa, ca; sincosf(0.5f * (phi + om), &sa, &ca);
        float sb, cb; sincosf(0.5f * (phi - om), &sb, &cb);
        sg[tid][0] =  ca * ct;  sg[tid][1] = -sa * ct;
        sg[tid][2] = -cb * st;  sg[tid][3] = -sb * st;
        sg[tid][4] =  cb * st;  sg[tid][5] = -sb * st;
        sg[tid][6] =  ca * ct;  sg[tid][7] =  sa * ct;
    }
    // stage W_pre into shared
    {
        const float4* W4 = (const float4*)Wpre;
        sW[tid]       = W4[tid];
        sW[tid + 256] = W4[tid + 256];
    }
    __syncthreads();

    // ---- Phase 0: build U via warp shfl evolution (warp j-pair) ----
    {
        int i = lane & 15;
        int j = 2 * warp + (lane >> 4);
        float re = (i == j) ? 1.0f : 0.0f;
        float im = 0.0f;
#pragma unroll
        for (int l = 0; l < NL; l++) {
#pragma unroll
            for (int w = 0; w < NQ; w++) {
                const float* g = sg[l * NQ + w];
                int m = 8 >> w;
                float pre_ = __shfl_xor_sync(0xffffffffu, re, m);
                float pim  = __shfl_xor_sync(0xffffffffu, im, m);
                bool low = (i & m) == 0;
                float orr = low ? g[0] : g[6];
                float oii = low ? g[1] : g[7];
                float crr = low ? g[2] : g[4];
                float cii = low ? g[3] : g[5];
                float nre = orr * re - oii * im + crr * pre_ - cii * pim;
                float nim = orr * im + oii * re + crr * pim + cii * pre_;
                re = nre; im = nim;
            }
            int r = l % (NQ - 1) + 1;
#pragma unroll
            for (int w = 0; w < NQ; w++) {
                int cmask = 8 >> w;
                int tmask = 8 >> ((w + r) & 3);
                int src_i = (i & cmask) ? (i ^ tmask) : i;
                int srcLane = (lane & 16) | src_i;
                re = __shfl_sync(0xffffffffu, re, srcLane);
                im = __shfl_sync(0xffffffffu, im, srcLane);
            }
        }
        sU[j * 16 + i] = make_float2(re, im);
    }

    // ---- Phase 1: GEMV, depth-4 software pipeline over 32 rows ----
    const int lbase = warp * 32;
    for (int rb = 0; rb < 32; rb += 4) {
        // D = row rb+3 (rb+3 <= 31 always)
#pragma unroll
        for (int jj = 0; jj < 4; jj++) D[jj] = xp[(rb + 3) * 128 + jj * 32];
        gemv_row(A, sW, spart, lbase + rb, lane);

        if (rb < 28) {
#pragma unroll
            for (int jj = 0; jj < 4; jj++) A[jj] = xp[(rb + 4) * 128 + jj * 32];
        }
        gemv_row(B, sW, spart, lbase + rb + 1, lane);

        if (rb < 28) {
#pragma unroll
            for (int jj = 0; jj < 4; jj++) B[jj] = xp[(rb + 5) * 128 + jj * 32];
        }
        gemv_row(C, sW, spart, lbase + rb + 2, lane);

        if (rb < 28) {
#pragma unroll
            for (int jj = 0; jj < 4; jj++) C[jj] = xp[(rb + 6) * 128 + jj * 32];
        }
        gemv_row(D, sW, spart, lbase + rb + 3, lane);
    }
    __syncthreads();

    // ---- Phase 2: thread-per-row quantum (round-3 proven path) ----
    float4 pre4 = make_float4(bpre[0], bpre[1], bpre[2], bpre[3]);
#pragma unroll
    for (int k = 0; k < 8; k++) {
        float4 p = spart[tid * 8 + ((tid + k) & 7)];
        pre4.x += p.x; pre4.y += p.y; pre4.z += p.z; pre4.w += p.w;
    }

    float cw[4], sw[4];
    {
        float pv[4] = {pre4.x, pre4.y, pre4.z, pre4.w};
#pragma unroll
        for (int w = 0; w < 4; w++) {
            float e = __expf(2.0f * pv[w]);
            float t = 1.0f - __fdividef(2.0f, e + 1.0f);
            float h = HPI_F * t;
            sw[w] = __sinf(h);
            cw[w] = __cosf(h);
        }
    }

    float p01[4], p23[4], v[16];
    p01[0] = cw[0] * cw[1]; p01[1] = cw[0] * sw[1];
    p01[2] = sw[0] * cw[1]; p01[3] = sw[0] * sw[1];
    p23[0] = cw[2] * cw[3]; p23[1] = cw[2] * sw[3];
    p23[2] = sw[2] * cw[3]; p23[3] = sw[2] * sw[3];
#pragma unroll
    for (int a = 0; a < 4; a++)
#pragma unroll
        for (int b = 0; b < 4; b++)
            v[a * 4 + b] = p01[a] * p23[b];

    ull acc64[16];
#pragma unroll
    for (int i = 0; i < 16; i++) acc64[i] = 0ull;
    const ull* sU64 = (const ull*)sU;
#pragma unroll
    for (int jcol = 0; jcol < 16; jcol++) {
        ull vj2 = pack2(v[jcol], v[jcol]);
#pragma unroll
        for (int i = 0; i < 16; i++)
            fma2(acc64[i], sU64[jcol * 16 + i], vj2, acc64[i]);
    }

    float pb[16];
#pragma unroll
    for (int i = 0; i < 16; i++) {
        float re, im; unpack2(acc64[i], re, im);
        pb[i] = re * re + im * im;
    }

    float q[4];
#pragma unroll
    for (int w = 0; w < 4; w++) {
        int m = 8 >> w;
        float s = 0.0f;
#pragma unroll
        for (int i = 0; i < 16; i++) s += (i & m) ? -pb[i] : pb[i];
        q[w] = s;
    }

#pragma unroll
    for (int c = 0; c < NC; c++) {
        float o = bpost[c];
#pragma unroll
        for (int w = 0; w < 4; w++) o = fmaf(q[w], Wpost[c * 4 + w], o);
        souts[tid * NC + c] = o;
    }
    __syncthreads();

    size_t obase = (size_t)row0 * NC;
    for (int i = tid; i < ROWS * NC; i += THREADS)
        out[obase + i] = souts[i];
}

// ---------------------------------------------------------------------------
extern "C" void kernel_launch(void* const* d_in, const int* in_sizes, int n_in,
                              void* d_out, int out_size) {
    const float* x     = (const float*)d_in[0];
    const float* Wpre  = (const float*)d_in[1];
    const float* bpre  = (const float*)d_in[2];
    const float* qw    = (const float*)d_in[3];
    const float* Wpost = (const float*)d_in[4];
    const float* bpost = (const float*)d_in[5];
    float* out = (float*)d_out;

    int B = in_sizes[0] / DIM;   // 65536
    vqc_fused_kernel<<<B / ROWS, THREADS>>>(x, Wpre, bpre, qw, Wpost, bpost, out);
}

// round 6
// speedup vs baseline: 1.3591x; 1.2369x over previous
#include <cuda_runtime.h>
#include <cstdint>

#define NQ 4
#define NL 6
#define NC 10
#define DIM 512
#define HPI_F 1.57079632679489661923f

#define THREADS 128
#define ROWS 128   // rows per block == THREADS (thread-per-row in phase 2)

typedef unsigned long long ull;

__device__ __forceinline__ void fma2(ull& d, ull a, ull b, ull c) {
    asm("fma.rn.f32x2 %0, %1, %2, %3;" : "=l"(d) : "l"(a), "l"(b), "l"(c));
}
__device__ __forceinline__ ull pack2(float lo, float hi) {
    ull r;
    asm("mov.b64 %0, {%1, %2};" : "=l"(r) : "r"(__float_as_uint(lo)), "r"(__float_as_uint(hi)));
    return r;
}
__device__ __forceinline__ void unpack2(ull v, float& lo, float& hi) {
    unsigned int a, b;
    asm("mov.b64 {%0, %1}, %2;" : "=r"(a), "=r"(b) : "l"(v));
    lo = __uint_as_float(a); hi = __uint_as_float(b);
}

// ---------------------------------------------------------------------------
// Fused kernel, 128-thread CTAs, 128 rows each, grid=512 (all resident).
// Phase 0: 4 warps build U; each warp evolves 4 basis columns (2 passes).
// Phase 1: warp-per-32-rows GEMV, W_pre in registers, depth-2 row prefetch,
//          2-level shfl reduce -> 8 partials/row in smem.
// Phase 2: thread-per-row quantum net + post linear, coalesced output.
// ---------------------------------------------------------------------------
__global__ __launch_bounds__(THREADS, 4) void vqc_fused_kernel(
    const float* __restrict__ x,
    const float* __restrict__ Wpre,
    const float* __restrict__ bpre,
    const float* __restrict__ qw,
    const float* __restrict__ Wpost,
    const float* __restrict__ bpost,
    float* __restrict__ out)
{
    __shared__ float  sg[24][8];
    __shared__ float2 sU[256];              // column-major [j][i]
    __shared__ float4 spart[ROWS * 8];      // 16KB partials
    __shared__ float  souts[ROWS * NC];     // 5KB

    const int tid  = threadIdx.x;
    const int lane = tid & 31;
    const int warp = tid >> 5;
    const int row0 = blockIdx.x * ROWS;
    const int wrow0 = row0 + warp * 32;

    // ---- prologue: first-row prefetch before the U chain ----
    const float4* x4 = (const float4*)x;
    float4 xv[4];
    {
        size_t base = (size_t)wrow0 * 128;
#pragma unroll
        for (int jj = 0; jj < 4; jj++) xv[jj] = x4[base + jj * 32 + lane];
    }
    // W_pre into registers
    const float4* W4 = (const float4*)Wpre;   // [4][128] float4
    float4 wr[4][4];
#pragma unroll
    for (int w = 0; w < 4; w++)
#pragma unroll
        for (int jj = 0; jj < 4; jj++)
            wr[w][jj] = W4[w * 128 + jj * 32 + lane];

    // gate coefficients
    if (tid < 24) {
        float phi = qw[tid * 3 + 0];
        float th  = qw[tid * 3 + 1];
        float om  = qw[tid * 3 + 2];
        float st, ct; sincosf(0.5f * th, &st, &ct);
        float sa, ca; sincosf(0.5f * (phi + om), &sa, &ca);
        float sb, cb; sincosf(0.5f * (phi - om), &sb, &cb);
        sg[tid][0] =  ca * ct;  sg[tid][1] = -sa * ct;   // g00
        sg[tid][2] = -cb * st;  sg[tid][3] = -sb * st;   // g01
        sg[tid][4] =  cb * st;  sg[tid][5] = -sb * st;   // g10
        sg[tid][6] =  ca * ct;  sg[tid][7] =  sa * ct;   // g11
    }
    __syncthreads();

    // ---- Phase 0: build U (each warp: 2 passes x 2 columns) ----
#pragma unroll
    for (int p = 0; p < 2; p++) {
        int i = lane & 15;
        int j = warp * 4 + p * 2 + (lane >> 4);
        float re = (i == j) ? 1.0f : 0.0f;
        float im = 0.0f;
#pragma unroll
        for (int l = 0; l < NL; l++) {
#pragma unroll
            for (int w = 0; w < NQ; w++) {
                const float* g = sg[l * NQ + w];
                int m = 8 >> w;
                float pre_ = __shfl_xor_sync(0xffffffffu, re, m);
                float pim  = __shfl_xor_sync(0xffffffffu, im, m);
                bool low = (i & m) == 0;
                float orr = low ? g[0] : g[6];
                float oii = low ? g[1] : g[7];
                float crr = low ? g[2] : g[4];
                float cii = low ? g[3] : g[5];
                float nre = orr * re - oii * im + crr * pre_ - cii * pim;
                float nim = orr * im + oii * re + crr * pim + cii * pre_;
                re = nre; im = nim;
            }
            int r = l % (NQ - 1) + 1;
#pragma unroll
            for (int w = 0; w < NQ; w++) {
                int cmask = 8 >> w;
                int tmask = 8 >> ((w + r) & 3);
                int src_i = (i & cmask) ? (i ^ tmask) : i;
                int srcLane = (lane & 16) | src_i;
                re = __shfl_sync(0xffffffffu, re, srcLane);
                im = __shfl_sync(0xffffffffu, im, srcLane);
            }
        }
        sU[j * 16 + i] = make_float2(re, im);
    }

    // ---- Phase 1: GEMV over 32 rows, depth-2 prefetch ----
#pragma unroll 4
    for (int rr = 0; rr < 32; rr++) {
        float4 nx[4];
        if (rr + 1 < 32) {
            size_t base = (size_t)(wrow0 + rr + 1) * 128;
#pragma unroll
            for (int jj = 0; jj < 4; jj++) nx[jj] = x4[base + jj * 32 + lane];
        }
        float acc[4] = {0.f, 0.f, 0.f, 0.f};
#pragma unroll
        for (int jj = 0; jj < 4; jj++) {
#pragma unroll
            for (int w = 0; w < 4; w++) {
                acc[w] = fmaf(xv[jj].x, wr[w][jj].x, acc[w]);
                acc[w] = fmaf(xv[jj].y, wr[w][jj].y, acc[w]);
                acc[w] = fmaf(xv[jj].z, wr[w][jj].z, acc[w]);
                acc[w] = fmaf(xv[jj].w, wr[w][jj].w, acc[w]);
            }
        }
#pragma unroll
        for (int w = 0; w < 4; w++) {
            acc[w] += __shfl_xor_sync(0xffffffffu, acc[w], 16);
            acc[w] += __shfl_xor_sync(0xffffffffu, acc[w], 8);
        }
        if (lane < 8) {
            int lrow = warp * 32 + rr;
            spart[lrow * 8 + lane] = make_float4(acc[0], acc[1], acc[2], acc[3]);
        }
#pragma unroll
        for (int jj = 0; jj < 4; jj++) xv[jj] = nx[jj];
    }
    __syncthreads();

    // ---- Phase 2: thread-per-row quantum ----
    float4 pre4 = make_float4(bpre[0], bpre[1], bpre[2], bpre[3]);
#pragma unroll
    for (int k = 0; k < 8; k++) {
        float4 p = spart[tid * 8 + ((tid + k) & 7)];   // bank-swizzled
        pre4.x += p.x; pre4.y += p.y; pre4.z += p.z; pre4.w += p.w;
    }

    float cw[4], sw[4];
    {
        float pv[4] = {pre4.x, pre4.y, pre4.z, pre4.w};
#pragma unroll
        for (int w = 0; w < 4; w++) {
            float e = __expf(2.0f * pv[w]);
            float t = 1.0f - __fdividef(2.0f, e + 1.0f);   // tanh
            float h = HPI_F * t;
            sw[w] = __sinf(h);
            cw[w] = __cosf(h);
        }
    }

    float p01[4], p23[4], v[16];
    p01[0] = cw[0] * cw[1]; p01[1] = cw[0] * sw[1];
    p01[2] = sw[0] * cw[1]; p01[3] = sw[0] * sw[1];
    p23[0] = cw[2] * cw[3]; p23[1] = cw[2] * sw[3];
    p23[2] = sw[2] * cw[3]; p23[3] = sw[2] * sw[3];
#pragma unroll
    for (int a = 0; a < 4; a++)
#pragma unroll
        for (int b = 0; b < 4; b++)
            v[a * 4 + b] = p01[a] * p23[b];

    ull acc64[16];
#pragma unroll
    for (int i = 0; i < 16; i++) acc64[i] = 0ull;
    const ull* sU64 = (const ull*)sU;
#pragma unroll
    for (int jcol = 0; jcol < 16; jcol++) {
        ull vj2 = pack2(v[jcol], v[jcol]);
#pragma unroll
        for (int i = 0; i < 16; i++)
            fma2(acc64[i], sU64[jcol * 16 + i], vj2, acc64[i]);
    }

    float pb[16];
#pragma unroll
    for (int i = 0; i < 16; i++) {
        float re, im; unpack2(acc64[i], re, im);
        pb[i] = re * re + im * im;
    }

    float q[4];
#pragma unroll
    for (int w = 0; w < 4; w++) {
        int m = 8 >> w;
        float s = 0.0f;
#pragma unroll
        for (int i = 0; i < 16; i++) s += (i & m) ? -pb[i] : pb[i];
        q[w] = s;
    }

#pragma unroll
    for (int c = 0; c < NC; c++) {
        float o = bpost[c];
#pragma unroll
        for (int w = 0; w < 4; w++) o = fmaf(q[w], Wpost[c * 4 + w], o);
        souts[tid * NC + c] = o;
    }
    __syncthreads();

    size_t obase = (size_t)row0 * NC;
    for (int i = tid; i < ROWS * NC; i += THREADS)
        out[obase + i] = souts[i];
}

// ---------------------------------------------------------------------------
extern "C" void kernel_launch(void* const* d_in, const int* in_sizes, int n_in,
                              void* d_out, int out_size) {
    const float* x     = (const float*)d_in[0];
    const float* Wpre  = (const float*)d_in[1];
    const float* bpre  = (const float*)d_in[2];
    const float* qw    = (const float*)d_in[3];
    const float* Wpost = (const float*)d_in[4];
    const float* bpost = (const float*)d_in[5];
    float* out = (float*)d_out;

    int B = in_sizes[0] / DIM;   // 65536
    vqc_fused_kernel<<<B / ROWS, THREADS>>>(x, Wpre, bpre, qw, Wpost, bpost, out);
}